// round 5
// baseline (speedup 1.0000x reference)
#include <cuda_runtime.h>

typedef unsigned long long ull;

#define N_NODES 50000
#define IN_FEAT 64
#define HID 32
#define GRIDP 4
#define NG 128

// ---------------- scratch (static device globals; no allocs allowed) --------
__device__ float g_h[N_NODES * HID];
__device__ float g_T[N_NODES * HID];
__device__ float g_acc[N_NODES * HID];
__device__ float g_sums[NG * HID];
__device__ float g_cnt[NG];
__device__ int   g_is64;

// ---------------- helpers ---------------------------------------------------
__device__ __forceinline__ int ldidx(const void* p, long long i, int is64) {
    if (is64) return (int)__ldg((const long long*)p + i);
    return __ldg((const int*)p + i);
}

__device__ __forceinline__ ull pk2(float a, float b) {
    ull r; asm("mov.b64 %0, {%1,%2};" : "=l"(r) : "f"(a), "f"(b)); return r;
}
// Packed dual-fp32 FMA / MUL (2 full-precision fp32 ops per issue slot)
__device__ __forceinline__ ull ffma2(ull a, ull b, ull c) {
    ull d; asm("fma.rn.f32x2 %0, %1, %2, %3;" : "=l"(d) : "l"(a), "l"(b), "l"(c));
    return d;
}
__device__ __forceinline__ ull fmul2(ull a, ull b) {
    ull d; asm("mul.rn.f32x2 %0, %1, %2;" : "=l"(d) : "l"(a), "l"(b));
    return d;
}
__device__ __forceinline__ float2 upk(ull v) {
    float2 r; asm("mov.b64 {%0,%1}, %2;" : "=f"(r.x), "=f"(r.y) : "l"(v));
    return r;
}

__device__ __forceinline__ float lrelu(float v) { return v > 0.f ? v : 0.01f * v; }

// ---------------- init: zero pool buffers + detect index dtype --------------
__global__ void k_init(const void* ei) {
    int j = blockIdx.x * blockDim.x + threadIdx.x;
    if (j < NG * HID) g_sums[j] = 0.f;
    if (j < NG) g_cnt[j] = 0.f;
    if (j == 0) {
        const unsigned* a = (const unsigned*)ei;
        int is64 = 1;
        for (int i = 0; i < 32; i++)
            if (a[2 * i + 1] != 0u) is64 = 0;
        g_is64 = is64;
    }
}

// ---------------- Fourier-KAN projection (cos/sin-lane f32x2) ----------------
// y[n,o] = sum_{i,g} cos((g+1)x[n,i])*W0[o,i,g] + sin((g+1)x[n,i])*W1[o,i,g]
// f32x2 lanes = (cos-part, sin-part):
//   acc[o] = ffma2( (cos_k, sin_k), (W0[o,k], W1[o,k]), acc[o] ),  y[o]=lo+hi.
// Chebyshev recurrence computed directly in packed form.
// Thread map (RACE-SAFE, R4 post-mortem): the two o-half threads of a node are
// lanes (li, li+16) of the SAME warp -> lockstep, so the MODE-2 read-modify-
// write of g_h / zeroing of g_acc can never interleave across the pair.
//   oh = lane>>4, node = blk*64 + warp*16 + (lane&15).
// Weights in shared: ull index k*HID + o = (W0[o,k], W1[o,k]).
// MODE 0: in = x,             out = g_h
// MODE 1: in = g_h,           out = g_T, zero g_acc
// MODE 2: in = lrelu(acc+h)   (writes h back), out = g_T, zero g_acc
template <int IN, int MODE>
__global__ __launch_bounds__(128) void k_kan(const float* __restrict__ xin,
                                             const float* __restrict__ W) {
    extern __shared__ float swf[];
    const int nW = 2 * HID * IN * GRIDP;
    // source j = ((s*HID + o)*IN + i)*GRIDP + g  ->  swf[(k*HID + o)*2 + s]
    for (int j = threadIdx.x; j < nW; j += blockDim.x) {
        int g = j & 3;
        int rem = j >> 2;
        int i = rem % IN;
        int o = (rem / IN) & (HID - 1);
        int s = rem / (IN * HID);
        swf[(((i * 4 + g) * HID) + o) * 2 + s] = W[j];
    }
    __syncthreads();

    int w = threadIdx.x >> 5;
    int lane = threadIdx.x & 31;
    int oh = lane >> 4;                      // which 16 outputs (same-warp pair)
    int node = blockIdx.x * 64 + w * 16 + (lane & 15);
    if (node >= N_NODES) return;

    const ull* swu = (const ull*)swf;

    ull acc[16];
#pragma unroll
    for (int t = 0; t < 16; t++) acc[t] = 0ull;

    const float4* xp = (MODE == 0) ? (const float4*)(xin + (size_t)node * IN)
                                   : (const float4*)(g_h + node * HID);
    const float4* ap = (const float4*)(g_acc + node * HID);
    float4* hp = (float4*)(g_h + node * HID);

    const ull NEGONE = pk2(-1.f, -1.f);
    const ull C10    = pk2(-1.f, 0.f);

#pragma unroll 1
    for (int ib = 0; ib < IN / 4; ib++) {
        float4 xv4;
        if (MODE == 2) {
            float4 m = ap[ib], h = hp[ib];
            xv4.x = lrelu(m.x + h.x); xv4.y = lrelu(m.y + h.y);
            xv4.z = lrelu(m.z + h.z); xv4.w = lrelu(m.w + h.w);
            hp[ib] = xv4;       // both o-half lanes store the identical value
        } else {
            xv4 = __ldg(xp + ib);
        }
#pragma unroll
        for (int u = 0; u < 4; u++) {
            int i = ib * 4 + u;
            float xv = (&xv4.x)[u];
            float s1, c1;
            __sincosf(xv, &s1, &c1);
            ull P[4];
            P[0] = pk2(c1, s1);
            float t2 = c1 + c1;
            ull T = pk2(t2, t2);
            P[1] = ffma2(T, P[0], C10);                 // (c2, s2)
            P[2] = ffma2(T, P[1], fmul2(P[0], NEGONE)); // (c3, s3)
            P[3] = ffma2(T, P[2], fmul2(P[1], NEGONE)); // (c4, s4)
#pragma unroll
            for (int g = 0; g < 4; g++) {
                const ulonglong2* wp =
                    (const ulonglong2*)(swu + ((size_t)(i * 4 + g) * HID) + oh * 16);
                ull Pg = P[g];
#pragma unroll
                for (int j = 0; j < 8; j++) {
                    ulonglong2 ww = wp[j];
                    acc[2 * j]     = ffma2(Pg, ww.x, acc[2 * j]);
                    acc[2 * j + 1] = ffma2(Pg, ww.y, acc[2 * j + 1]);
                }
            }
        }
    }

    // y[o] = cos-part + sin-part
    float* outbase = ((MODE == 0) ? g_h : g_T) + node * HID + oh * 16;
    float4* po = (float4*)outbase;
#pragma unroll
    for (int j = 0; j < 4; j++) {
        float2 e0 = upk(acc[4 * j]);
        float2 e1 = upk(acc[4 * j + 1]);
        float2 e2 = upk(acc[4 * j + 2]);
        float2 e3 = upk(acc[4 * j + 3]);
        po[j] = make_float4(e0.x + e0.y, e1.x + e1.y, e2.x + e2.y, e3.x + e3.y);
    }

    if (MODE != 0) {  // zero the scatter-buffer half-row this thread owns
        float4 z = make_float4(0.f, 0.f, 0.f, 0.f);
        float4* az = (float4*)(g_acc + node * HID + oh * 16);
        az[0] = z; az[1] = z; az[2] = z; az[3] = z;
    }
}

// ---------------- edge scatter: acc[dst] += T[src] --------------------------
__global__ void k_scatter(const void* __restrict__ ei, int E) {
    long long gid = (long long)blockIdx.x * blockDim.x + threadIdx.x;
    int e = (int)(gid >> 3);
    int q = (int)(gid & 7);
    if (e >= E) return;
    int is64 = g_is64;
    int src = ldidx(ei, e, is64);
    int dst = ldidx(ei, (long long)E + e, is64);
    float4 v = __ldg((const float4*)g_T + src * (HID / 4) + q);
    float* p = g_acc + dst * HID + q * 4;
    asm volatile("red.global.add.v4.f32 [%0], {%1, %2, %3, %4};"
                 :: "l"(p), "f"(v.x), "f"(v.y), "f"(v.z), "f"(v.w)
                 : "memory");
}

// ---------------- pooling (fused final leaky-relu + residual) ---------------
__global__ void k_pool(const void* __restrict__ batch) {
    int warp = (blockIdx.x * blockDim.x + threadIdx.x) >> 5;
    int lane = threadIdx.x & 31;
    if (warp >= N_NODES) return;
    int b = ldidx(batch, warp, g_is64);
    float m = g_acc[warp * HID + lane];
    float h = g_h[warp * HID + lane];
    float v = lrelu(m + h);
    atomicAdd(&g_sums[b * HID + lane], v);
    if (lane == 0) atomicAdd(&g_cnt[b], 1.f);
}

// ---------------- readout: sigmoid(KAN_linear(mean_pool)) -------------------
__global__ void k_readout(const float* __restrict__ Wout,
                          const float* __restrict__ bout,
                          float* __restrict__ out) {
    int g = threadIdx.x;
    if (g >= NG) return;
    float cnt = fmaxf(g_cnt[g], 1.f);
    float inv = 1.f / cnt;
    float acc = 0.f;
#pragma unroll
    for (int c = 0; c < HID; c++) {
        float y = g_sums[g * HID + c] * inv;
        float s, co;
        __sincosf(y, &s, &co);
        acc = fmaf(co, Wout[c], acc);
        acc = fmaf(s, Wout[HID + c], acc);
    }
    acc += bout[0];
    out[g] = 1.f / (1.f + __expf(-acc));
}

// ---------------- launch ----------------------------------------------------
extern "C" void kernel_launch(void* const* d_in, const int* in_sizes, int n_in,
                              void* d_out, int out_size) {
    const float* x      = (const float*)d_in[0];
    const void*  ei     = d_in[1];
    const void*  batch  = d_in[2];
    const float* W_in   = (const float*)d_in[3];
    const float* W_conv = (const float*)d_in[4];
    const float* W_out  = (const float*)d_in[5];
    const float* b_out  = (const float*)d_in[6];
    float* out = (float*)d_out;

    int E = in_sizes[1] / 2;

    cudaFuncSetAttribute(k_kan<IN_FEAT, 0>,
                         cudaFuncAttributeMaxDynamicSharedMemorySize, 65536);

    k_init<<<16, 256>>>(ei);

    int nb = (N_NODES + 63) / 64;   // 64 nodes per 128-thread block (2 thr/node)
    k_kan<IN_FEAT, 0><<<nb, 128, 2 * HID * IN_FEAT * GRIDP * sizeof(float)>>>(x, W_in);

    const int convW = 2 * HID * HID * GRIDP;
    long long tthreads = (long long)E * 8;
    int sb = (int)((tthreads + 255) / 256);

    // layer 0: transform h -> T, scatter
    k_kan<HID, 1><<<nb, 128, convW * sizeof(float)>>>(nullptr, W_conv);
    k_scatter<<<sb, 256>>>(ei, E);

    // layer 1: fused lrelu(acc+h) -> transform -> T, scatter
    k_kan<HID, 2><<<nb, 128, convW * sizeof(float)>>>(nullptr, W_conv + convW);
    k_scatter<<<sb, 256>>>(ei, E);

    k_pool<<<(N_NODES + 7) / 8, 256>>>(batch);
    k_readout<<<1, 128>>>(W_out, b_out, out);
}

// round 7
// speedup vs baseline: 1.8116x; 1.8116x over previous
#include <cuda_runtime.h>
#include <cuda_bf16.h>
#include <cstdint>

#define N_NODES 50000
#define IN_FEAT 64
#define HID 32
#define NG 128

// ---------------- scratch (static device globals; no allocs allowed) --------
__device__ float g_h[N_NODES * HID];
__device__ float g_T[N_NODES * HID];
__device__ float g_acc[N_NODES * HID];
__device__ float g_sums[NG * HID];
__device__ float g_cnt[NG];
__device__ int   g_is64;
// prepped bf16 hi/lo weights, layout [o][k], k = i*8 + s*4 + g
__device__ __nv_bfloat16 g_W1h[32 * 512];
__device__ __nv_bfloat16 g_W1l[32 * 512];
__device__ __nv_bfloat16 g_Wch[2 * 32 * 256];
__device__ __nv_bfloat16 g_Wcl[2 * 32 * 256];

// ---------------- helpers ---------------------------------------------------
__device__ __forceinline__ int ldidx(const void* p, long long i, int is64) {
    if (is64) return (int)__ldg((const long long*)p + i);
    return __ldg((const int*)p + i);
}
__device__ __forceinline__ float lrelu(float v) { return v > 0.f ? v : 0.01f * v; }
__device__ __forceinline__ uint32_t smem_u32(const void* p) {
    uint32_t a;
    asm("{ .reg .u64 t; cvta.to.shared.u64 t, %1; cvt.u32.u64 %0, t; }"
        : "=r"(a) : "l"(p));
    return a;
}
// pack (lo, hi) floats into a bf16x2 word (lo in bits [0,16))
__device__ __forceinline__ uint32_t bfpack(float lo, float hi) {
    uint32_t d;
    asm("cvt.rn.bf16x2.f32 %0, %1, %2;" : "=r"(d) : "f"(hi), "f"(lo));
    return d;
}
__device__ __forceinline__ void ldmatrix_x4(uint32_t* r, uint32_t addr) {
    asm volatile("ldmatrix.sync.aligned.m8n8.x4.shared.b16 {%0,%1,%2,%3}, [%4];"
                 : "=r"(r[0]), "=r"(r[1]), "=r"(r[2]), "=r"(r[3]) : "r"(addr));
}
__device__ __forceinline__ void ldmatrix_x2(uint32_t& r0, uint32_t& r1, uint32_t addr) {
    asm volatile("ldmatrix.sync.aligned.m8n8.x2.shared.b16 {%0,%1}, [%2];"
                 : "=r"(r0), "=r"(r1) : "r"(addr));
}
__device__ __forceinline__ void mma16816(float* d, const uint32_t* a,
                                         uint32_t b0, uint32_t b1) {
    asm volatile("mma.sync.aligned.m16n8k16.row.col.f32.bf16.bf16.f32 "
                 "{%0,%1,%2,%3}, {%4,%5,%6,%7}, {%8,%9}, {%0,%1,%2,%3};"
                 : "+f"(d[0]), "+f"(d[1]), "+f"(d[2]), "+f"(d[3])
                 : "r"(a[0]), "r"(a[1]), "r"(a[2]), "r"(a[3]), "r"(b0), "r"(b1));
}

// ---------------- init: zero pool buffers + detect index dtype --------------
__global__ void k_init(const void* ei) {
    int j = blockIdx.x * blockDim.x + threadIdx.x;
    if (j < NG * HID) g_sums[j] = 0.f;
    if (j < NG) g_cnt[j] = 0.f;
    if (j == 0) {
        const unsigned* a = (const unsigned*)ei;
        int is64 = 1;
        for (int i = 0; i < 32; i++)
            if (a[2 * i + 1] != 0u) is64 = 0;
        g_is64 = is64;
    }
}

// ---------------- weight prep: rearrange + bf16 hi/lo split ------------------
// k-order: k = i*8 + s*4 + g  (s=0 cos, s=1 sin; harmonic multiplier g+1)
__global__ void k_prep(const float* __restrict__ W_in, const float* __restrict__ W_conv) {
    int j = blockIdx.x * blockDim.x + threadIdx.x;
    float w; int dst;
    __nv_bfloat16 *Dh, *Dl;
    if (j < 16384) {                     // W_in (2,32,64,4)
        int g = j & 3, i = (j >> 2) & 63, o = (j >> 8) & 31, s = j >> 13;
        w = W_in[j];
        dst = o * 512 + i * 8 + s * 4 + g;
        Dh = g_W1h; Dl = g_W1l;
    } else if (j < 32768) {              // W_conv (2,2,32,32,4)
        int jj = j - 16384;
        int l = jj >> 13;
        int r = jj & 8191;
        int g = r & 3, i = (r >> 2) & 31, o = (r >> 7) & 31, s = r >> 12;
        w = W_conv[jj];
        dst = o * 256 + i * 8 + s * 4 + g;
        Dh = g_Wch + l * 8192; Dl = g_Wcl + l * 8192;
    } else return;
    __nv_bfloat16 h = __float2bfloat16(w);
    Dh[dst] = h;
    Dl[dst] = __float2bfloat16(w - __bfloat162float(h));
}

// ---------------- KAN layer via warp-level bf16 MMA (mma.sync) ---------------
// Y[n,o] = sum_k Phi[n,k]*W[o,k]; Phi = [cos((g+1)x), sin((g+1)x)], k=i*8+s*4+g.
// bf16 3-term split: D = Ph*Wh + Ph*Wl + Pl*Wh, fp32 accumulate.
// Block = 256 thr = 8 warps; warp w owns node rows [blk*128+16w, +16) x all 32 o.
// Per 128-k chunk: warp computes Phi hi/lo for its own rows into private smem
// (pitch 272B -> ldmatrix conflict-free), syncwarp, then 8x k16 MMA steps.
// Weight smem tile: row (kt*32+o) of 32B = W[o][16 k]; plain ldmatrix.x2 of
// these rows yields the col-major B fragment directly.
// MODE 0: in = x,            out = g_h
// MODE 1: in = g_h,          out = g_T, zero g_acc
// MODE 2: in = lrelu(acc+h)  (writes h back), out = g_T, zero g_acc
template <int IN, int MODE>
__global__ __launch_bounds__(256) void k_kan_mma(const float* __restrict__ xin, int layer) {
    constexpr int K = IN * 8;
    constexpr int NCH = IN / 16;            // 128-k chunks
    constexpr int WBYTES = K * 64;          // weight tile bytes (one of hi/lo)
    constexpr int PH_PITCH = 272;           // 256B row + 16B pad (17x16)
    constexpr int PH_WARP = 16 * PH_PITCH;  // 4352B per warp
    extern __shared__ char smem[];
    const uint32_t SB = smem_u32(smem);
    const uint32_t SM_WH = 0, SM_WL = WBYTES, SM_PH = 2 * WBYTES,
                   SM_PL = SM_PH + 8 * PH_WARP;

    int tid = threadIdx.x;
    int w = tid >> 5, lane = tid & 31;

    // ---- stage weights (permuted 32-bit word copy) ----
    const __nv_bfloat16* Wh = (MODE == 0) ? g_W1h : (g_Wch + layer * 8192);
    const __nv_bfloat16* Wl = (MODE == 0) ? g_W1l : (g_Wcl + layer * 8192);
    const uint32_t* WhU = (const uint32_t*)Wh;
    const uint32_t* WlU = (const uint32_t*)Wl;
    uint32_t* swh = (uint32_t*)(smem + SM_WH);
    uint32_t* swl = (uint32_t*)(smem + SM_WL);
    for (int wdx = tid; wdx < K * 16; wdx += 256) {
        int kt = wdx >> 8;                  // 256 words per k16-tile
        int o = (wdx >> 3) & 31;
        int seg = wdx & 7;
        int src = (o * K + kt * 16 + seg * 2) >> 1;
        int dst = (kt * 32 + o) * 8 + seg;
        swh[dst] = WhU[src];
        swl[dst] = WlU[src];
    }
    __syncthreads();

    // ---- per-lane constant addresses ----
    int nloc = lane & 15, half = lane >> 4;
    int node = blockIdx.x * 128 + w * 16 + nloc;
    int nodeC = node < N_NODES ? node : N_NODES - 1;
    bool nvalid = node < N_NODES;
    // Phi store base for this lane's (row, i-half)
    uint32_t phiRowH = SB + SM_PH + w * PH_WARP + nloc * PH_PITCH + half * 128;
    uint32_t phiRowL = SB + SM_PL + w * PH_WARP + nloc * PH_PITCH + half * 128;
    // A-ldmatrix address (row r, k-base kb) for this lane
    int ar = (lane & 7) + (lane & 8);
    uint32_t aBaseH = SB + SM_PH + w * PH_WARP + ar * PH_PITCH + (lane >> 4) * 16;
    uint32_t aBaseL = SB + SM_PL + w * PH_WARP + ar * PH_PITCH + (lane >> 4) * 16;
    // B-ldmatrix per-lane offset (lanes 0-15 meaningful)
    uint32_t bLane = (uint32_t)((lane & 7) * 32 + ((lane >> 3) & 1) * 16);

    float acc[4][4];
#pragma unroll
    for (int nt = 0; nt < 4; nt++)
#pragma unroll
        for (int j = 0; j < 4; j++) acc[nt][j] = 0.f;

#pragma unroll 1
    for (int c = 0; c < NCH; c++) {
        // ---- compute Phi chunk for this warp's 16 rows ----
        int ibase = c * 16 + half * 8;
        float xv[8];
        if (MODE == 0) {
            const float4* xp = (const float4*)(xin + (size_t)nodeC * IN) + (ibase >> 2);
            float4 a = __ldg(xp), b = __ldg(xp + 1);
            xv[0] = a.x; xv[1] = a.y; xv[2] = a.z; xv[3] = a.w;
            xv[4] = b.x; xv[5] = b.y; xv[6] = b.z; xv[7] = b.w;
        } else if (MODE == 1) {
            const float4* hp = (const float4*)(g_h + nodeC * HID) + (ibase >> 2);
            float4 a = hp[0], b = hp[1];
            xv[0] = a.x; xv[1] = a.y; xv[2] = a.z; xv[3] = a.w;
            xv[4] = b.x; xv[5] = b.y; xv[6] = b.z; xv[7] = b.w;
        } else {
            float4* hp = (float4*)(g_h + nodeC * HID) + (ibase >> 2);
            const float4* ap = (const float4*)(g_acc + nodeC * HID) + (ibase >> 2);
#pragma unroll
            for (int q = 0; q < 2; q++) {
                float4 m = ap[q], h = hp[q];
                float4 r;
                r.x = lrelu(m.x + h.x); r.y = lrelu(m.y + h.y);
                r.z = lrelu(m.z + h.z); r.w = lrelu(m.w + h.w);
                if (nvalid) hp[q] = r;       // h_{l+1} writeback (once per elem)
                xv[q * 4 + 0] = r.x; xv[q * 4 + 1] = r.y;
                xv[q * 4 + 2] = r.z; xv[q * 4 + 3] = r.w;
            }
        }
#pragma unroll
        for (int u = 0; u < 8; u++) {
            float s1, c1;
            __sincosf(xv[u], &s1, &c1);
            float t2 = c1 + c1;
            float c2 = fmaf(t2, c1, -1.f), s2 = t2 * s1;
            float c3 = fmaf(t2, c2, -c1),  s3 = fmaf(t2, s2, -s1);
            float c4 = fmaf(t2, c3, -c2),  s4 = fmaf(t2, s3, -s2);
            float v[8] = { c1, c2, c3, c4, s1, s2, s3, s4 };
            uint32_t hw[4], lw[4];
#pragma unroll
            for (int j = 0; j < 4; j++) {
                hw[j] = bfpack(v[2 * j], v[2 * j + 1]);
                float r0 = v[2 * j]     - __uint_as_float(hw[j] << 16);
                float r1 = v[2 * j + 1] - __uint_as_float(hw[j] & 0xFFFF0000u);
                lw[j] = bfpack(r0, r1);
            }
            asm volatile("st.shared.v4.b32 [%0], {%1,%2,%3,%4};"
                         :: "r"(phiRowH + u * 16), "r"(hw[0]), "r"(hw[1]), "r"(hw[2]), "r"(hw[3]) : "memory");
            asm volatile("st.shared.v4.b32 [%0], {%1,%2,%3,%4};"
                         :: "r"(phiRowL + u * 16), "r"(lw[0]), "r"(lw[1]), "r"(lw[2]), "r"(lw[3]) : "memory");
        }
        __syncwarp();

        // ---- MMA over this chunk: 8 k16 steps ----
#pragma unroll 1
        for (int kk = 0; kk < 8; kk++) {
            uint32_t ah[4], al[4];
            ldmatrix_x4(ah, aBaseH + kk * 32);
            ldmatrix_x4(al, aBaseL + kk * 32);
            uint32_t bt = SB + (uint32_t)((c * 8 + kk) * 1024) + bLane;
#pragma unroll
            for (int nt = 0; nt < 4; nt++) {
                uint32_t bh0, bh1, bl0, bl1;
                ldmatrix_x2(bh0, bh1, SM_WH + bt + nt * 256);
                ldmatrix_x2(bl0, bl1, SM_WL + bt + nt * 256);
                mma16816(acc[nt], ah, bh0, bh1);
                mma16816(acc[nt], ah, bl0, bl1);
                mma16816(acc[nt], al, bh0, bh1);
            }
        }
        __syncwarp();   // before next chunk overwrites Phi
    }

    // ---- write D ----
    float* outbase = (MODE == 0) ? g_h : g_T;
    int gq = lane >> 2, tg = lane & 3;
    int row0 = blockIdx.x * 128 + w * 16 + gq;
    int row1 = row0 + 8;
    if (row0 < N_NODES) {
        float* p = outbase + row0 * HID + 2 * tg;
#pragma unroll
        for (int nt = 0; nt < 4; nt++)
            *(float2*)(p + nt * 8) = make_float2(acc[nt][0], acc[nt][1]);
    }
    if (row1 < N_NODES) {
        float* p = outbase + row1 * HID + 2 * tg;
#pragma unroll
        for (int nt = 0; nt < 4; nt++)
            *(float2*)(p + nt * 8) = make_float2(acc[nt][2], acc[nt][3]);
    }
    if (MODE != 0 && nvalid) {   // zero scatter buffer (each lane: half a row)
        float4 z = make_float4(0.f, 0.f, 0.f, 0.f);
        float4* az = (float4*)(g_acc + node * HID + half * 16);
        az[0] = z; az[1] = z;
        az[2] = z; az[3] = z;
    }
}

// ---------------- edge scatter: acc[dst] += T[src] --------------------------
__global__ void k_scatter(const void* __restrict__ ei, int E) {
    long long gid = (long long)blockIdx.x * blockDim.x + threadIdx.x;
    int e = (int)(gid >> 3);
    int q = (int)(gid & 7);
    if (e >= E) return;
    int is64 = g_is64;
    int src = ldidx(ei, e, is64);
    int dst = ldidx(ei, (long long)E + e, is64);
    float4 v = __ldg((const float4*)g_T + src * (HID / 4) + q);
    float* p = g_acc + dst * HID + q * 4;
    asm volatile("red.global.add.v4.f32 [%0], {%1, %2, %3, %4};"
                 :: "l"(p), "f"(v.x), "f"(v.y), "f"(v.z), "f"(v.w)
                 : "memory");
}

// ---------------- pooling (fused final leaky-relu + residual) ---------------
__global__ void k_pool(const void* __restrict__ batch) {
    int warp = (blockIdx.x * blockDim.x + threadIdx.x) >> 5;
    int lane = threadIdx.x & 31;
    if (warp >= N_NODES) return;
    int b = ldidx(batch, warp, g_is64);
    float m = g_acc[warp * HID + lane];
    float h = g_h[warp * HID + lane];
    float v = lrelu(m + h);
    atomicAdd(&g_sums[b * HID + lane], v);
    if (lane == 0) atomicAdd(&g_cnt[b], 1.f);
}

// ---------------- readout: sigmoid(KAN_linear(mean_pool)) -------------------
__global__ void k_readout(const float* __restrict__ Wout,
                          const float* __restrict__ bout,
                          float* __restrict__ out) {
    int g = threadIdx.x;
    if (g >= NG) return;
    float cnt = fmaxf(g_cnt[g], 1.f);
    float inv = 1.f / cnt;
    float acc = 0.f;
#pragma unroll
    for (int c = 0; c < HID; c++) {
        float y = g_sums[g * HID + c] * inv;
        float s, co;
        __sincosf(y, &s, &co);
        acc = fmaf(co, Wout[c], acc);
        acc = fmaf(s, Wout[HID + c], acc);
    }
    acc += bout[0];
    out[g] = 1.f / (1.f + __expf(-acc));
}

// ---------------- launch ----------------------------------------------------
extern "C" void kernel_launch(void* const* d_in, const int* in_sizes, int n_in,
                              void* d_out, int out_size) {
    const float* x      = (const float*)d_in[0];
    const void*  ei     = d_in[1];
    const void*  batch  = d_in[2];
    const float* W_in   = (const float*)d_in[3];
    const float* W_conv = (const float*)d_in[4];
    const float* W_out  = (const float*)d_in[5];
    const float* b_out  = (const float*)d_in[6];
    float* out = (float*)d_out;

    int E = in_sizes[1] / 2;

    const int SM1 = 2 * 512 * 64 + 2 * 8 * 16 * 272;   // 65536 + 69632 = 135168
    const int SMC = 2 * 256 * 64 + 2 * 8 * 16 * 272;   // 32768 + 69632 = 102400
    cudaFuncSetAttribute(k_kan_mma<IN_FEAT, 0>, cudaFuncAttributeMaxDynamicSharedMemorySize, SM1);
    cudaFuncSetAttribute(k_kan_mma<HID, 1>,     cudaFuncAttributeMaxDynamicSharedMemorySize, SMC);
    cudaFuncSetAttribute(k_kan_mma<HID, 2>,     cudaFuncAttributeMaxDynamicSharedMemorySize, SMC);

    k_init<<<16, 256>>>(ei);
    k_prep<<<128, 256>>>(W_in, W_conv);

    int nb = (N_NODES + 127) / 128;        // 391 tiles of 128 nodes
    long long tthreads = (long long)E * 8;
    int sb = (int)((tthreads + 255) / 256);

    k_kan_mma<IN_FEAT, 0><<<nb, 256, SM1>>>(x, 0);

    k_kan_mma<HID, 1><<<nb, 256, SMC>>>(nullptr, 0);
    k_scatter<<<sb, 256>>>(ei, E);

    k_kan_mma<HID, 2><<<nb, 256, SMC>>>(nullptr, 1);
    k_scatter<<<sb, 256>>>(ei, E);

    k_pool<<<(N_NODES + 7) / 8, 256>>>(batch);
    k_readout<<<1, 128>>>(W_out, b_out, out);
}